// round 2
// baseline (speedup 1.0000x reference)
#include <cuda_runtime.h>
#include <cstdint>

typedef unsigned long long u64;

#define Bn 1024
#define Tn 512
#define Ln 64
#define Nn 8
#define Hn 128
#define DIn 32
#define DOn 16
#define RROWS 8
#define PAIRS 4
#define NCTA (Bn / RROWS)   /* 128 */
#define NTHR 128
#define XFULL ((size_t)Bn * Tn * DOn)
#define HP (Hn + 2)         /* padded hidden buffers: keeps 16B align, de-conflicts r2 */

// ---------------- shared memory layout (~228.7 KB) ---------------------------
struct __align__(16) Smem {
    float fW1t[Hn][68];    // f_W1 z-part transposed [j][k]; stride 68 == 4 (mod 32): conflict-free LDS.128
    float fW1t0[Hn];       // f_W1 t-row
    float fW2t[Hn][132];   // f_W2 transposed; 132 == 4 (mod 32)
    float gW1t[Hn][68];
    float gW1t0[Hn];
    float gW2t[Hn][132];
    float2 z2[PAIRS][Ln];  // state, row-pairs packed: .x = row 2p, .y = row 2p+1
    float2 h1[PAIRS][HP];
    float2 h2[PAIRS][HP];
    float2 fo[PAIRS][Ln];  // drift output f
    float2 dws[PAIRS][Nn]; // dW * sqrt(dt), pair-packed
    float rW2s[Hn * DOn];
    float tss[Tn];
};

// ---------------- f32x2 packed helpers ---------------------------------------
__device__ __forceinline__ u64 dup2f(float v) {
    u64 r; asm("mov.b64 %0,{%1,%1};" : "=l"(r) : "f"(v)); return r;
}
__device__ __forceinline__ u64 pk2(float lo, float hi) {
    u64 r; asm("mov.b64 %0,{%1,%2};" : "=l"(r) : "f"(lo), "f"(hi)); return r;
}
__device__ __forceinline__ void unpk2(u64 v, float& lo, float& hi) {
    asm("mov.b64 {%0,%1},%2;" : "=f"(lo), "=f"(hi) : "l"(v));
}
__device__ __forceinline__ u64 f2fma(u64 a, u64 b, u64 c) {
    u64 d; asm("fma.rn.f32x2 %0,%1,%2,%3;" : "=l"(d) : "l"(a), "l"(b), "l"(c)); return d;
}

// softplus(x) = max(x,0) + log1p(exp(-|x|))
__device__ __forceinline__ float softplus1(float x) {
    float e = __expf(-fabsf(x));
    return fmaxf(x, 0.f) + 0.69314718055994531f * __log2f(1.f + e);
}
// tanh(x) = 1 - 2/(exp(2x)+1); saturates correctly
__device__ __forceinline__ float tanh1(float x) {
    float e = __expf(2.f * x);
    return 1.f - __fdividef(2.f, e + 1.f);
}

// ---------------- layer kernels ----------------------------------------------
// Input layer with [t, z] input (K = 1 + 64). Thread j owns hidden neuron j.
__device__ __forceinline__ void layer_tz(const float (&Wt)[Hn][68], const float (&Wt0)[Hn],
                                         float bias, float tcur,
                                         const float2 (&acts)[PAIRS][Ln],
                                         float2 (&outp)[PAIRS][HP], int tid)
{
    u64 acc[PAIRS];
    float s0 = fmaf(Wt0[tid], tcur, bias);
    u64 d0 = dup2f(s0);
#pragma unroll
    for (int p = 0; p < PAIRS; p++) acc[p] = d0;
#pragma unroll 4
    for (int c = 0; c < Ln / 4; c++) {
        float4 w = *(const float4*)&Wt[tid][4 * c];
        u64 w0 = dup2f(w.x), w1 = dup2f(w.y), w2 = dup2f(w.z), w3 = dup2f(w.w);
#pragma unroll
        for (int p = 0; p < PAIRS; p++) {
            ulonglong2 a0 = *(const ulonglong2*)&acts[p][4 * c];
            ulonglong2 a1 = *(const ulonglong2*)&acts[p][4 * c + 2];
            acc[p] = f2fma(w0, a0.x, acc[p]);
            acc[p] = f2fma(w1, a0.y, acc[p]);
            acc[p] = f2fma(w2, a1.x, acc[p]);
            acc[p] = f2fma(w3, a1.y, acc[p]);
        }
    }
#pragma unroll
    for (int p = 0; p < PAIRS; p++) {
        float lo, hi; unpk2(acc[p], lo, hi);
        outp[p][tid] = make_float2(softplus1(lo), softplus1(hi));
    }
}

// Hidden->hidden layer, K = 128.
__device__ __forceinline__ void layer_h(const float (&Wt)[Hn][132], float bias,
                                        const float2 (&acts)[PAIRS][HP],
                                        float2 (&outp)[PAIRS][HP], int tid)
{
    u64 acc[PAIRS];
    u64 d0 = dup2f(bias);
#pragma unroll
    for (int p = 0; p < PAIRS; p++) acc[p] = d0;
#pragma unroll 4
    for (int c = 0; c < Hn / 4; c++) {
        float4 w = *(const float4*)&Wt[tid][4 * c];
        u64 w0 = dup2f(w.x), w1 = dup2f(w.y), w2 = dup2f(w.z), w3 = dup2f(w.w);
#pragma unroll
        for (int p = 0; p < PAIRS; p++) {
            ulonglong2 a0 = *(const ulonglong2*)&acts[p][4 * c];
            ulonglong2 a1 = *(const ulonglong2*)&acts[p][4 * c + 2];
            acc[p] = f2fma(w0, a0.x, acc[p]);
            acc[p] = f2fma(w1, a0.y, acc[p]);
            acc[p] = f2fma(w2, a1.x, acc[p]);
            acc[p] = f2fma(w3, a1.y, acc[p]);
        }
    }
#pragma unroll
    for (int p = 0; p < PAIRS; p++) {
        float lo, hi; unpk2(acc[p], lo, hi);
        outp[p][tid] = make_float2(softplus1(lo), softplus1(hi));
    }
}

// Drift output layer: 64 outputs, tanh. Thread (half = tid>>6, l = tid&63) does
// pairs {2*half, 2*half+1}. f_W3 streamed (k-major -> coalesced per warp).
__device__ __forceinline__ void layer_f3(const float* __restrict__ fW3, float bias,
                                         const float2 (&h2)[PAIRS][HP],
                                         float2 (&fo)[PAIRS][Ln], int tid)
{
    int l = tid & (Ln - 1);
    int p0 = (tid >> 6) * 2;
    u64 a0 = dup2f(bias), a1 = a0;
#pragma unroll 8
    for (int k = 0; k < Hn; k++) {
        float w = __ldg(fW3 + k * Ln + l);
        u64 wd = dup2f(w);
        a0 = f2fma(wd, *(const u64*)&h2[p0][k], a0);
        a1 = f2fma(wd, *(const u64*)&h2[p0 + 1][k], a1);
    }
    float lo, hi;
    unpk2(a0, lo, hi); fo[p0][l]     = make_float2(tanh1(lo), tanh1(hi));
    unpk2(a1, lo, hi); fo[p0 + 1][l] = make_float2(tanh1(lo), tanh1(hi));
}

// Fused readout at time index tidx: x = relu(z @ rW1 + rb1) @ rW2 + rb2
__device__ __forceinline__ void readout(int tidx, const float* __restrict__ rW1,
                                        float rb1v, float rb2v, Smem& sm, int tid,
                                        int rowbase, float* __restrict__ out)
{
    u64 acc[PAIRS];
    u64 bi = dup2f(rb1v);
#pragma unroll
    for (int p = 0; p < PAIRS; p++) acc[p] = bi;
#pragma unroll 8
    for (int l = 0; l < Ln; l++) {
        float w = __ldg(rW1 + l * Hn + tid);   // (64,128) row-major -> coalesced
        u64 wd = dup2f(w);
#pragma unroll
        for (int p = 0; p < PAIRS; p++)
            acc[p] = f2fma(wd, *(const u64*)&sm.z2[p][l], acc[p]);
    }
#pragma unroll
    for (int p = 0; p < PAIRS; p++) {
        float lo, hi; unpk2(acc[p], lo, hi);
        sm.h1[p][tid] = make_float2(fmaxf(lo, 0.f), fmaxf(hi, 0.f));
    }
    __syncthreads();
    int r = tid >> 4, d = tid & 15;
    const float* hp = ((const float*)&sm.h1[r >> 1][0]) + (r & 1);
    float a = rb2v;
#pragma unroll 8
    for (int k = 0; k < Hn; k++)
        a = fmaf(hp[2 * k], sm.rW2s[k * DOn + d], a);
    size_t row = (size_t)rowbase + r;
    out[(row * Tn + tidx) * DOn + d] = a;
    if ((tidx & 7) == 0)
        out[XFULL + (row * (Tn / 8) + (tidx >> 3)) * DOn + d] = a;
    __syncthreads();   // protect h1 against next step's overwrite
}

// ---------------- main persistent kernel -------------------------------------
__global__ void __launch_bounds__(NTHR, 1)
sde_kernel(const float* __restrict__ init_noise, const float* __restrict__ dw_noise,
           const float* __restrict__ ts,   const float* __restrict__ embW,
           const float* __restrict__ embb, const float* __restrict__ fW1,
           const float* __restrict__ fb1,  const float* __restrict__ fW2,
           const float* __restrict__ fb2,  const float* __restrict__ fW3,
           const float* __restrict__ fb3,  const float* __restrict__ gW1,
           const float* __restrict__ gb1,  const float* __restrict__ gW2,
           const float* __restrict__ gb2,  const float* __restrict__ gW3,
           const float* __restrict__ gb3,  const float* __restrict__ rW1,
           const float* __restrict__ rb1,  const float* __restrict__ rW2,
           const float* __restrict__ rb2,  float* __restrict__ out)
{
    extern __shared__ __align__(16) char smraw[];
    Smem& sm = *reinterpret_cast<Smem*>(smraw);
    const int tid = threadIdx.x;
    const int rowbase = blockIdx.x * RROWS;

    // ---- stage SMEM-resident weights (once) ----
#pragma unroll 4
    for (int k = 0; k < Ln; k++) {
        sm.fW1t[tid][k] = fW1[(k + 1) * Hn + tid];
        sm.gW1t[tid][k] = gW1[(k + 1) * Hn + tid];
    }
    sm.fW1t0[tid] = fW1[tid];
    sm.gW1t0[tid] = gW1[tid];
#pragma unroll 4
    for (int k = 0; k < Hn; k++) {
        sm.fW2t[tid][k] = fW2[k * Hn + tid];
        sm.gW2t[tid][k] = gW2[k * Hn + tid];
    }
    for (int i = tid; i < Hn * DOn; i += NTHR) sm.rW2s[i] = rW2[i];
    for (int i = tid; i < Tn; i += NTHR) sm.tss[i] = ts[i];

    // per-thread register biases
    const float bf1 = fb1[tid], bf2 = fb2[tid], bg1 = gb1[tid], bg2 = gb2[tid];
    const float bf3 = fb3[tid & (Ln - 1)];
    float bg3v[4];
#pragma unroll
    for (int i = 0; i < 4; i++) bg3v[i] = gb3[4 * tid + i];
    const float rb1v = rb1[tid], rb2v = rb2[tid & 15];

    // ---- z0 = init_noise @ emb_W + emb_b ----
    {
        int l = tid & (Ln - 1);
        int p0 = (tid >> 6) * 2;
#pragma unroll
        for (int pp = 0; pp < 2; pp++) {
            int p = p0 + pp;
            float ax = embb[l], ay = ax;
#pragma unroll 4
            for (int i = 0; i < DIn; i++) {
                float w = embW[i * Ln + l];
                ax = fmaf(init_noise[(rowbase + 2 * p) * DIn + i], w, ax);
                ay = fmaf(init_noise[(rowbase + 2 * p + 1) * DIn + i], w, ay);
            }
            sm.z2[p][l] = make_float2(ax, ay);
        }
    }
    __syncthreads();
    readout(0, rW1, rb1v, rb2v, sm, tid, rowbase, out);

    // ---- 511 sequential Euler-Maruyama steps with fused readout ----
    for (int s = 0; s < Tn - 1; s++) {
        const float tcur = sm.tss[s];
        const float dt = sm.tss[s + 1] - tcur;
        const float sq = sqrtf(dt);
        if (tid < 32) {   // Brownian increments, pair-packed
            int p = tid >> 3, n = tid & 7;
            int b0 = rowbase + 2 * p;
            const float* dwp = dw_noise + ((size_t)s * Bn + b0) * Nn + n;
            sm.dws[p][n] = make_float2(dwp[0] * sq, dwp[Nn] * sq);
        }
        // no sync needed here: dws consumed only after several syncs below

        // f MLP layers 1,2
        layer_tz(sm.fW1t, sm.fW1t0, bf1, tcur, sm.z2, sm.h1, tid);
        __syncthreads();
        layer_h(sm.fW2t, bf2, sm.h1, sm.h2, tid);
        __syncthreads();
        // f layer 3 (reads f-h2) and g layer 1 (overwrites h1) together
        layer_f3(fW3, bf3, sm.h2, sm.fo, tid);
        layer_tz(sm.gW1t, sm.gW1t0, bg1, tcur, sm.z2, sm.h1, tid);
        __syncthreads();
        layer_h(sm.gW2t, bg2, sm.h1, sm.h2, tid);
        __syncthreads();

        // g layer 3 fused with einsum + z update.
        // Thread owns outputs o = 4*tid .. 4*tid+3 (l = tid>>1; n-half = (tid&1)*4).
        {
            u64 acc[PAIRS][4];
#pragma unroll
            for (int p = 0; p < PAIRS; p++)
#pragma unroll
                for (int i = 0; i < 4; i++) acc[p][i] = dup2f(bg3v[i]);

            const float* gp = gW3 + 4 * tid;
#pragma unroll 2
            for (int k = 0; k < Hn; k += 2) {
                float4 wa = *(const float4*)(gp + (size_t)k * (Ln * Nn));
                float4 wb = *(const float4*)(gp + (size_t)(k + 1) * (Ln * Nn));
                u64 wa0 = dup2f(wa.x), wa1 = dup2f(wa.y), wa2 = dup2f(wa.z), wa3 = dup2f(wa.w);
                u64 wb0 = dup2f(wb.x), wb1 = dup2f(wb.y), wb2 = dup2f(wb.z), wb3 = dup2f(wb.w);
#pragma unroll
                for (int p = 0; p < PAIRS; p++) {
                    ulonglong2 a = *(const ulonglong2*)&sm.h2[p][k]; // h2[p][k], h2[p][k+1]
                    acc[p][0] = f2fma(wa0, a.x, acc[p][0]);
                    acc[p][1] = f2fma(wa1, a.x, acc[p][1]);
                    acc[p][2] = f2fma(wa2, a.x, acc[p][2]);
                    acc[p][3] = f2fma(wa3, a.x, acc[p][3]);
                    acc[p][0] = f2fma(wb0, a.y, acc[p][0]);
                    acc[p][1] = f2fma(wb1, a.y, acc[p][1]);
                    acc[p][2] = f2fma(wb2, a.y, acc[p][2]);
                    acc[p][3] = f2fma(wb3, a.y, acc[p][3]);
                }
            }
            // tanh, multiply by dW, partial einsum over this thread's 4 n's
            int nbase = (tid & 1) * 4;
            u64 part[PAIRS];
#pragma unroll
            for (int p = 0; p < PAIRS; p++) {
                u64 pa = dup2f(0.f);
#pragma unroll
                for (int i = 0; i < 4; i++) {
                    float lo, hi; unpk2(acc[p][i], lo, hi);
                    u64 tv = pk2(tanh1(lo), tanh1(hi));
                    pa = f2fma(tv, *(const u64*)&sm.dws[p][nbase + i], pa);
                }
                part[p] = pa;
            }
            // combine neighbor thread's other 4 n's, then even thread updates z
            const u64 one2 = dup2f(1.f);
            u64 dt2 = dup2f(dt);
            int l = tid >> 1;
#pragma unroll
            for (int p = 0; p < PAIRS; p++) {
                u64 other = __shfl_xor_sync(0xffffffffu, part[p], 1);
                if ((tid & 1) == 0) {
                    u64 z = *(const u64*)&sm.z2[p][l];
                    z = f2fma(*(const u64*)&sm.fo[p][l], dt2, z);   // + f*dt
                    z = f2fma(part[p], one2, z);                    // + own einsum half
                    z = f2fma(other, one2, z);                      // + neighbor half
                    *(u64*)&sm.z2[p][l] = z;
                }
            }
        }
        __syncthreads();
        readout(s + 1, rW1, rb1v, rb2v, sm, tid, rowbase, out);
    }
}

extern "C" void kernel_launch(void* const* d_in, const int* in_sizes, int n_in,
                              void* d_out, int out_size) {
    (void)in_sizes; (void)n_in; (void)out_size;
    cudaFuncSetAttribute(sde_kernel, cudaFuncAttributeMaxDynamicSharedMemorySize,
                         (int)sizeof(Smem));
    sde_kernel<<<NCTA, NTHR, sizeof(Smem)>>>(
        (const float*)d_in[0],  (const float*)d_in[1],  (const float*)d_in[2],
        (const float*)d_in[3],  (const float*)d_in[4],  (const float*)d_in[5],
        (const float*)d_in[6],  (const float*)d_in[7],  (const float*)d_in[8],
        (const float*)d_in[9],  (const float*)d_in[10], (const float*)d_in[11],
        (const float*)d_in[12], (const float*)d_in[13], (const float*)d_in[14],
        (const float*)d_in[15], (const float*)d_in[16], (const float*)d_in[17],
        (const float*)d_in[18], (const float*)d_in[19], (const float*)d_in[20],
        (float*)d_out);
}